// round 2
// baseline (speedup 1.0000x reference)
#include <cuda_runtime.h>
#include <math.h>

// Problem constants
constexpr int cB  = 4;
constexpr int cN  = 8192;
constexpr int cH  = 1024;
constexpr int cNH = 16;
constexpr int cM  = 64;
constexpr int cD  = 64;
constexpr int cHM = cNH * cM;   // 1024

// ---------------- scratch (device globals; no runtime allocation) ----------
__device__ float g_S   [(size_t)cB * cN * cHM];  // scores -> weights (in place) 134MB
__device__ float g_At  [cH * cHM];               // A transposed [j][hm]
__device__ float g_c   [cHM];                    // per-hm score bias (from b_kv)
__device__ float g_T   [cB * cN * cNH];          // temperature
__device__ float g_norm[cB * cHM];               // slice_norm
__device__ float g_y   [(size_t)cB * cHM * cH];  // y = w^T x
__device__ float g_st  [cB * cNH * cM * cD];     // slice_token
__device__ float g_ost [cB * cNH * cM * cD];     // out_slice_token
__device__ float g_Z   [(size_t)cB * cHM * cH];  // Z = ost @ w_out_h

// ---------------------------------------------------------------------------
// Generic 128x128x16 SGEMM, 256 threads, 8x8 per thread (split 4+4), fp32.
// C[m,n] = sum_k A(m,k) B(k,n) (+ bias[n]).  B stored [K,N]. A stored [M,K]
// (A_KM=false) or [K,M] (A_KM=true). Batched via blockIdx.z strides.
// ---------------------------------------------------------------------------
template<bool A_KM, bool HAS_BIAS>
__global__ void __launch_bounds__(256)
sgemm_kernel(const float* __restrict__ A, const float* __restrict__ Bm,
             float* __restrict__ C, const float* __restrict__ bias,
             int Mdim, int Ndim, int Kdim, int lda, int ldb, int ldc,
             long long sA, long long sB, long long sC)
{
    A  += (long long)blockIdx.z * sA;
    Bm += (long long)blockIdx.z * sB;
    C  += (long long)blockIdx.z * sC;

    __shared__ float As[16][128];
    __shared__ float Bs[16][128];

    const int tid = threadIdx.x;
    const int tx  = tid & 15;   // col group
    const int ty  = tid >> 4;   // row group
    const int m0  = blockIdx.y * 128;
    const int n0  = blockIdx.x * 128;

    float acc[8][8];
#pragma unroll
    for (int i = 0; i < 8; i++)
#pragma unroll
        for (int j = 0; j < 8; j++) acc[i][j] = 0.f;

    for (int k0 = 0; k0 < Kdim; k0 += 16) {
        if (A_KM) {
#pragma unroll
            for (int r = 0; r < 2; r++) {
                int lin = tid + r * 256;          // 0..511
                int k   = lin >> 5;               // 0..15
                int m4  = (lin & 31) << 2;        // 0..124
                float4 v = *(const float4*)(A + (long long)(k0 + k) * lda + m0 + m4);
                *(float4*)(&As[k][m4]) = v;
            }
        } else {
#pragma unroll
            for (int r = 0; r < 2; r++) {
                int lin = tid + r * 256;
                int m   = lin >> 2;               // 0..127
                int k4  = (lin & 3) << 2;         // 0,4,8,12
                float4 v = *(const float4*)(A + (long long)(m0 + m) * lda + k0 + k4);
                As[k4 + 0][m] = v.x; As[k4 + 1][m] = v.y;
                As[k4 + 2][m] = v.z; As[k4 + 3][m] = v.w;
            }
        }
#pragma unroll
        for (int r = 0; r < 2; r++) {
            int lin = tid + r * 256;
            int k   = lin >> 5;
            int n4  = (lin & 31) << 2;
            float4 v = *(const float4*)(Bm + (long long)(k0 + k) * ldb + n0 + n4);
            *(float4*)(&Bs[k][n4]) = v;
        }
        __syncthreads();

#pragma unroll
        for (int kk = 0; kk < 16; kk++) {
            float4 a0 = *(const float4*)(&As[kk][ty * 4]);
            float4 a1 = *(const float4*)(&As[kk][64 + ty * 4]);
            float4 b0 = *(const float4*)(&Bs[kk][tx * 4]);
            float4 b1 = *(const float4*)(&Bs[kk][64 + tx * 4]);
            float av[8] = {a0.x, a0.y, a0.z, a0.w, a1.x, a1.y, a1.z, a1.w};
            float bv[8] = {b0.x, b0.y, b0.z, b0.w, b1.x, b1.y, b1.z, b1.w};
#pragma unroll
            for (int i = 0; i < 8; i++)
#pragma unroll
                for (int j = 0; j < 8; j++)
                    acc[i][j] += av[i] * bv[j];
        }
        __syncthreads();
    }

#pragma unroll
    for (int i = 0; i < 8; i++) {
        int m = m0 + (i < 4 ? ty * 4 + i : 64 + ty * 4 + (i - 4));
#pragma unroll
        for (int jh = 0; jh < 2; jh++) {
            int n = n0 + jh * 64 + tx * 4;
            float4 v;
            v.x = acc[i][jh * 4 + 0]; v.y = acc[i][jh * 4 + 1];
            v.z = acc[i][jh * 4 + 2]; v.w = acc[i][jh * 4 + 3];
            if (HAS_BIAS) {
                float4 bb = *(const float4*)(bias + n);
                v.x += bb.x; v.y += bb.y; v.z += bb.z; v.w += bb.w;
            }
            *(float4*)(C + (long long)m * ldc + n) = v;
        }
    }
}

// ---------------------------------------------------------------------------
// prep: At[j][hm] = sum_d xq[hm*64+d] * w_kv[j*2048 + (hm&~63)+d]; c[hm]
// ---------------------------------------------------------------------------
__global__ void __launch_bounds__(256)
k_prep(const float* __restrict__ xq, const float* __restrict__ w_kv,
       const float* __restrict__ b_kv)
{
    int idx = blockIdx.x * 256 + threadIdx.x;     // < 1024*1024
    int j   = idx >> 10;
    int hm  = idx & 1023;
    int hbase = (hm >> 6) << 6;
    const float* xr = xq + (size_t)hm * 64;
    const float* wr = w_kv + (size_t)j * 2048 + hbase;
    float acc = 0.f;
#pragma unroll 8
    for (int d = 0; d < 64; d++) acc += xr[d] * wr[d];
    g_At[(size_t)j * 1024 + hm] = acc;
    if (j == 0) {
        const float* br = b_kv + hbase;
        float cc = 0.f;
        for (int d = 0; d < 64; d++) cc += xr[d] * br[d];
        g_c[hm] = cc;
    }
}

// ---------------------------------------------------------------------------
// temperature: T[bn,h] = 0.5 + softplus(x[bn,:] @ w_temp[:,h] + b_temp[h])
// ---------------------------------------------------------------------------
__global__ void __launch_bounds__(256)
k_temp(const float* __restrict__ x, const float* __restrict__ w_temp,
       const float* __restrict__ b_temp)
{
    int bn = blockIdx.x;
    __shared__ float xs[1024];
    __shared__ float part[256];
    int t = threadIdx.x;
    *(float4*)&xs[t * 4] = *(const float4*)(x + (size_t)bn * 1024 + t * 4);
    __syncthreads();
    int j0 = t >> 4, head = t & 15;
    float acc = 0.f;
#pragma unroll 8
    for (int i = 0; i < 64; i++) {
        int j = j0 + (i << 4);
        acc += xs[j] * w_temp[j * 16 + head];
    }
    part[t] = acc;
    __syncthreads();
    if (t < 16) {
        float s = 0.f;
#pragma unroll
        for (int g = 0; g < 16; g++) s += part[g * 16 + t];
        s += b_temp[t];
        float sp = fmaxf(s, 0.f) + log1pf(expf(-fabsf(s)));
        g_T[(size_t)bn * 16 + t] = 0.5f + sp;
    }
}

__global__ void k_zero_norm()
{
    int i = blockIdx.x * 256 + threadIdx.x;
    if (i < cB * cHM) g_norm[i] = 0.f;
}

// ---------------------------------------------------------------------------
// softmax over m (in-place on g_S) + slice_norm accumulation.
// block = 32 rows (b,n); thread t owns hm = 4t..4t+3 (same head group of 16).
// ---------------------------------------------------------------------------
__global__ void __launch_bounds__(256)
k_softmax()
{
    int t   = threadIdx.x;
    int bn0 = blockIdx.x * 32;
    int b   = bn0 / cN;
    float nacc[4] = {0.f, 0.f, 0.f, 0.f};
    int head = t >> 4;
    for (int r = 0; r < 32; r++) {
        size_t bn = (size_t)bn0 + r;
        float4 s = *(float4*)(g_S + bn * 1024 + t * 4);
        float temp  = g_T[bn * 16 + head];
        float inv_t = 1.0f / temp;
        float mx = fmaxf(fmaxf(s.x, s.y), fmaxf(s.z, s.w));
#pragma unroll
        for (int o = 8; o >= 1; o >>= 1)
            mx = fmaxf(mx, __shfl_xor_sync(0xffffffffu, mx, o, 16));
        float4 e;
        e.x = expf((s.x - mx) * inv_t);
        e.y = expf((s.y - mx) * inv_t);
        e.z = expf((s.z - mx) * inv_t);
        e.w = expf((s.w - mx) * inv_t);
        float sum = e.x + e.y + e.z + e.w;
#pragma unroll
        for (int o = 8; o >= 1; o >>= 1)
            sum += __shfl_xor_sync(0xffffffffu, sum, o, 16);
        float inv = 1.0f / sum;
        e.x *= inv; e.y *= inv; e.z *= inv; e.w *= inv;
        *(float4*)(g_S + bn * 1024 + t * 4) = e;
        nacc[0] += e.x; nacc[1] += e.y; nacc[2] += e.z; nacc[3] += e.w;
    }
    float* np = g_norm + b * 1024 + t * 4;
    atomicAdd(np + 0, nacc[0]);
    atomicAdd(np + 1, nacc[1]);
    atomicAdd(np + 2, nacc[2]);
    atomicAdd(np + 3, nacc[3]);
}

// ---------------------------------------------------------------------------
// slice_token: st[m,d] = (y[m,:]@Wv_h[:,d] + norm[m]*bv[d]) / (norm[m]+1e-5)
// one block per (b,h); 64x64 output, K=1024, 4x4 per thread.
// ---------------------------------------------------------------------------
__global__ void __launch_bounds__(256)
k_st(const float* __restrict__ w_kv, const float* __restrict__ b_kv)
{
    int z = blockIdx.x;            // b*16+h
    int b = z >> 4, h = z & 15;
    const float* Yb = g_y + ((size_t)b * 1024 + h * 64) * 1024;
    const float* Wv = w_kv + 1024 + h * 64;
    __shared__ float As[16][64];
    __shared__ float Bs[16][64];
    int t = threadIdx.x;
    int tyy = t >> 4, txx = t & 15;
    float acc[4][4] = {};
    for (int k0 = 0; k0 < 1024; k0 += 16) {
        {
            int m = t >> 2, k4 = (t & 3) << 2;
            float4 v = *(const float4*)(Yb + (size_t)m * 1024 + k0 + k4);
            As[k4 + 0][m] = v.x; As[k4 + 1][m] = v.y;
            As[k4 + 2][m] = v.z; As[k4 + 3][m] = v.w;
        }
        {
            int k = t >> 4, n4 = (t & 15) << 2;
            float4 v = *(const float4*)(Wv + (size_t)(k0 + k) * 2048 + n4);
            *(float4*)&Bs[k][n4] = v;
        }
        __syncthreads();
#pragma unroll
        for (int kk = 0; kk < 16; kk++) {
            float4 a  = *(const float4*)&As[kk][tyy * 4];
            float4 bb = *(const float4*)&Bs[kk][txx * 4];
            float av[4] = {a.x, a.y, a.z, a.w};
            float bv[4] = {bb.x, bb.y, bb.z, bb.w};
#pragma unroll
            for (int i = 0; i < 4; i++)
#pragma unroll
                for (int jj = 0; jj < 4; jj++) acc[i][jj] += av[i] * bv[jj];
        }
        __syncthreads();
    }
#pragma unroll
    for (int i = 0; i < 4; i++) {
        int m = tyy * 4 + i;
        float nrm = g_norm[b * 1024 + h * 64 + m];
        float inv = 1.0f / (nrm + 1e-5f);
#pragma unroll
        for (int jj = 0; jj < 4; jj++) {
            int d = txx * 4 + jj;
            float bvv = b_kv[1024 + h * 64 + d];
            g_st[((size_t)z * 64 + m) * 64 + d] = (acc[i][jj] + nrm * bvv) * inv;
        }
    }
}

// ---------------------------------------------------------------------------
// tiny intra-slice attention: qkv proj + elementwise softmax over d -> ost
// one block per (b,h,m), 64 threads (one per output d).
// ---------------------------------------------------------------------------
__global__ void __launch_bounds__(64)
k_qkv(const float* __restrict__ qkv_proj)
{
    int z = blockIdx.x;               // (b*16+h)*64 + m
    int h = (z >> 6) & 15;
    int d = threadIdx.x;
    __shared__ float st[64];
    __shared__ float ex[64];
    st[d] = g_st[(size_t)z * 64 + d];
    __syncthreads();
    const float* P = qkv_proj + (size_t)h * 64 * 192;
    float q = 0.f, k = 0.f, v = 0.f;
#pragma unroll 8
    for (int j = 0; j < 64; j++) {
        float s = st[j];
        const float* pr = P + j * 192;
        q += s * pr[d];
        k += s * pr[64 + d];
        v += s * pr[128 + d];
    }
    float dot = q * k * 0.125f;       // SCALE = D^-0.5 = 1/8
    ex[d] = dot;
    __syncthreads();
    float mx = -1e30f;
    for (int j = 0; j < 64; j++) mx = fmaxf(mx, ex[j]);
    __syncthreads();
    float e = expf(dot - mx);
    ex[d] = e;
    __syncthreads();
    float sum = 0.f;
    for (int j = 0; j < 64; j++) sum += ex[j];
    g_ost[(size_t)z * 64 + d] = (e / sum) * v;
}

// ---------------------------------------------------------------------------
// Z[b,hm,j] = sum_d ost[b,h,m,d] * w_out[h*64+d, j]
// grid (16 j-chunks, 64 bh), K=64 single shot, 4x4 per thread.
// ---------------------------------------------------------------------------
__global__ void __launch_bounds__(256)
k_zmat(const float* __restrict__ w_out)
{
    int z  = blockIdx.y;              // b*16+h
    int jc = blockIdx.x;              // 0..15
    int b = z >> 4, h = z & 15;
    __shared__ float As[64][64];
    __shared__ float Bs[64][64];
    int t = threadIdx.x;
#pragma unroll
    for (int r = 0; r < 4; r++) {
        int lin = t + r * 256;
        int row = lin >> 4;           // 0..63
        int c4  = (lin & 15) << 2;    // 0..60
        float4 v = *(const float4*)(g_ost + ((size_t)z * 64 + row) * 64 + c4);
        As[c4 + 0][row] = v.x; As[c4 + 1][row] = v.y;
        As[c4 + 2][row] = v.z; As[c4 + 3][row] = v.w;
        float4 w = *(const float4*)(w_out + (size_t)(h * 64 + row) * 1024 + jc * 64 + c4);
        *(float4*)&Bs[row][c4] = w;
    }
    __syncthreads();
    int tyy = t >> 4, txx = t & 15;
    float acc[4][4] = {};
#pragma unroll
    for (int kk = 0; kk < 64; kk++) {
        float4 a  = *(const float4*)&As[kk][tyy * 4];
        float4 bb = *(const float4*)&Bs[kk][txx * 4];
        float av[4] = {a.x, a.y, a.z, a.w};
        float bv[4] = {bb.x, bb.y, bb.z, bb.w};
#pragma unroll
        for (int i = 0; i < 4; i++)
#pragma unroll
            for (int jj = 0; jj < 4; jj++) acc[i][jj] += av[i] * bv[jj];
    }
#pragma unroll
    for (int i = 0; i < 4; i++)
#pragma unroll
        for (int jj = 0; jj < 4; jj++)
            g_Z[((size_t)b * 1024 + h * 64 + tyy * 4 + i) * 1024 + jc * 64 + txx * 4 + jj]
                = acc[i][jj];
}

// ---------------------------------------------------------------------------
extern "C" void kernel_launch(void* const* d_in, const int* in_sizes, int n_in,
                              void* d_out, int out_size)
{
    (void)in_sizes; (void)n_in; (void)out_size;
    const float* x      = (const float*)d_in[0];
    // d_in[1] = c : unused by the reference
    const float* w_kv   = (const float*)d_in[2];
    const float* b_kv   = (const float*)d_in[3];
    const float* w_temp = (const float*)d_in[4];
    const float* b_temp = (const float*)d_in[5];
    const float* xq     = (const float*)d_in[6];
    const float* qkv_p  = (const float*)d_in[7];
    const float* w_out  = (const float*)d_in[8];
    const float* b_out  = (const float*)d_in[9];
    float* out = (float*)d_out;

    float *pS, *pAt, *pc, *py, *pZ;
    cudaGetSymbolAddress((void**)&pS,  g_S);
    cudaGetSymbolAddress((void**)&pAt, g_At);
    cudaGetSymbolAddress((void**)&pc,  g_c);
    cudaGetSymbolAddress((void**)&py,  g_y);
    cudaGetSymbolAddress((void**)&pZ,  g_Z);

    // 1. head-projection precompute
    k_prep<<<4096, 256>>>(xq, w_kv, b_kv);
    // 2. temperatures
    k_temp<<<cB * cN, 256>>>(x, w_temp, b_temp);
    // 3. scores: S[bn,hm] = x @ At + c   (M=32768,N=1024,K=1024)
    sgemm_kernel<false, true><<<dim3(8, 256, 1), 256>>>(
        x, pAt, pS, pc, cB * cN, cHM, cH, 1024, 1024, 1024, 0, 0, 0);
    // 4. zero norms, softmax over m + norm accumulation
    k_zero_norm<<<16, 256>>>();
    k_softmax<<<(cB * cN) / 32, 256>>>();
    // 5. y = w^T x per batch  (M=1024,N=1024,K=8192)
    sgemm_kernel<true, false><<<dim3(8, 8, cB), 256>>>(
        pS, x, py, nullptr, cHM, cH, cN, 1024, 1024, 1024,
        (long long)cN * cHM, (long long)cN * cH, (long long)cHM * cH);
    // 6. slice_token
    k_st<<<cB * cNH, 256>>>(w_kv, b_kv);
    // 7. tiny qkv + elementwise attention
    k_qkv<<<cB * cNH * cM, 64>>>(qkv_p);
    // 8. Z = ost @ w_out_h
    k_zmat<<<dim3(16, cB * cNH), 256>>>(w_out);
    // 9. out = w @ Z + b_out per batch  (M=8192,N=1024,K=1024)
    sgemm_kernel<false, true><<<dim3(8, 64, cB), 256>>>(
        pS, pZ, out, b_out, cN, cH, cHM, 1024, 1024, 1024,
        (long long)cN * cHM, (long long)cHM * cH, (long long)cN * cH);
}

// round 3
// speedup vs baseline: 1.0012x; 1.0012x over previous
#include <cuda_runtime.h>
#include <math.h>

// Problem constants
constexpr int cB  = 4;
constexpr int cN  = 8192;
constexpr int cH  = 1024;
constexpr int cNH = 16;
constexpr int cM  = 64;
constexpr int cD  = 64;
constexpr int cHM = cNH * cM;   // 1024

// ---------------- scratch (device globals; no runtime allocation) ----------
__device__ float g_S   [(size_t)cB * cN * cHM];  // scores -> weights (in place) 134MB
__device__ float g_At  [cH * cHM];               // A transposed [j][hm]
__device__ float g_c   [cHM];                    // per-hm score bias (from b_kv)
__device__ float g_T   [cB * cN * cNH];          // temperature
__device__ float g_norm[cB * cHM];               // slice_norm
__device__ float g_y   [(size_t)cB * cHM * cH];  // y = w^T x
__device__ float g_st  [cB * cNH * cM * cD];     // slice_token
__device__ float g_ost [cB * cNH * cM * cD];     // out_slice_token
__device__ float g_Z   [(size_t)cB * cHM * cH];  // Z = ost @ w_out_h

// ---------------------------------------------------------------------------
// Generic 128x128x16 SGEMM, 256 threads, 8x8 per thread (split 4+4), fp32.
// C[m,n] = sum_k A(m,k) B(k,n) (+ bias[n]).  B stored [K,N]. A stored [M,K]
// (A_KM=false) or [K,M] (A_KM=true). Batched via blockIdx.z strides.
// ---------------------------------------------------------------------------
template<bool A_KM, bool HAS_BIAS>
__global__ void __launch_bounds__(256)
sgemm_kernel(const float* __restrict__ A, const float* __restrict__ Bm,
             float* __restrict__ C, const float* __restrict__ bias,
             int Mdim, int Ndim, int Kdim, int lda, int ldb, int ldc,
             long long sA, long long sB, long long sC)
{
    A  += (long long)blockIdx.z * sA;
    Bm += (long long)blockIdx.z * sB;
    C  += (long long)blockIdx.z * sC;

    __shared__ float As[16][128];
    __shared__ float Bs[16][128];

    const int tid = threadIdx.x;
    const int tx  = tid & 15;   // col group
    const int ty  = tid >> 4;   // row group
    const int m0  = blockIdx.y * 128;
    const int n0  = blockIdx.x * 128;

    float acc[8][8];
#pragma unroll
    for (int i = 0; i < 8; i++)
#pragma unroll
        for (int j = 0; j < 8; j++) acc[i][j] = 0.f;

    for (int k0 = 0; k0 < Kdim; k0 += 16) {
        if (A_KM) {
#pragma unroll
            for (int r = 0; r < 2; r++) {
                int lin = tid + r * 256;          // 0..511
                int k   = lin >> 5;               // 0..15
                int m4  = (lin & 31) << 2;        // 0..124
                float4 v = *(const float4*)(A + (long long)(k0 + k) * lda + m0 + m4);
                *(float4*)(&As[k][m4]) = v;
            }
        } else {
#pragma unroll
            for (int r = 0; r < 2; r++) {
                int lin = tid + r * 256;
                int m   = lin >> 2;               // 0..127
                int k4  = (lin & 3) << 2;         // 0,4,8,12
                float4 v = *(const float4*)(A + (long long)(m0 + m) * lda + k0 + k4);
                As[k4 + 0][m] = v.x; As[k4 + 1][m] = v.y;
                As[k4 + 2][m] = v.z; As[k4 + 3][m] = v.w;
            }
        }
#pragma unroll
        for (int r = 0; r < 2; r++) {
            int lin = tid + r * 256;
            int k   = lin >> 5;
            int n4  = (lin & 31) << 2;
            float4 v = *(const float4*)(Bm + (long long)(k0 + k) * ldb + n0 + n4);
            *(float4*)(&Bs[k][n4]) = v;
        }
        __syncthreads();

#pragma unroll
        for (int kk = 0; kk < 16; kk++) {
            float4 a0 = *(const float4*)(&As[kk][ty * 4]);
            float4 a1 = *(const float4*)(&As[kk][64 + ty * 4]);
            float4 b0 = *(const float4*)(&Bs[kk][tx * 4]);
            float4 b1 = *(const float4*)(&Bs[kk][64 + tx * 4]);
            float av[8] = {a0.x, a0.y, a0.z, a0.w, a1.x, a1.y, a1.z, a1.w};
            float bv[8] = {b0.x, b0.y, b0.z, b0.w, b1.x, b1.y, b1.z, b1.w};
#pragma unroll
            for (int i = 0; i < 8; i++)
#pragma unroll
                for (int j = 0; j < 8; j++)
                    acc[i][j] += av[i] * bv[j];
        }
        __syncthreads();
    }

#pragma unroll
    for (int i = 0; i < 8; i++) {
        int m = m0 + (i < 4 ? ty * 4 + i : 64 + ty * 4 + (i - 4));
#pragma unroll
        for (int jh = 0; jh < 2; jh++) {
            int n = n0 + jh * 64 + tx * 4;
            float4 v;
            v.x = acc[i][jh * 4 + 0]; v.y = acc[i][jh * 4 + 1];
            v.z = acc[i][jh * 4 + 2]; v.w = acc[i][jh * 4 + 3];
            if (HAS_BIAS) {
                float4 bb = *(const float4*)(bias + n);
                v.x += bb.x; v.y += bb.y; v.z += bb.z; v.w += bb.w;
            }
            *(float4*)(C + (long long)m * ldc + n) = v;
        }
    }
}

// ---------------------------------------------------------------------------
// prep: At[j][hm] = sum_d xq[hm*64+d] * w_kv[j*2048 + (hm&~63)+d]; c[hm]
// ---------------------------------------------------------------------------
__global__ void __launch_bounds__(256)
k_prep(const float* __restrict__ xq, const float* __restrict__ w_kv,
       const float* __restrict__ b_kv)
{
    int idx = blockIdx.x * 256 + threadIdx.x;     // < 1024*1024
    int j   = idx >> 10;
    int hm  = idx & 1023;
    int hbase = (hm >> 6) << 6;
    const float* xr = xq + (size_t)hm * 64;
    const float* wr = w_kv + (size_t)j * 2048 + hbase;
    float acc = 0.f;
#pragma unroll 8
    for (int d = 0; d < 64; d++) acc += xr[d] * wr[d];
    g_At[(size_t)j * 1024 + hm] = acc;
    if (j == 0) {
        const float* br = b_kv + hbase;
        float cc = 0.f;
        for (int d = 0; d < 64; d++) cc += xr[d] * br[d];
        g_c[hm] = cc;
    }
}

// ---------------------------------------------------------------------------
// temperature: T[bn,h] = 0.5 + softplus(x[bn,:] @ w_temp[:,h] + b_temp[h])
// ---------------------------------------------------------------------------
__global__ void __launch_bounds__(256)
k_temp(const float* __restrict__ x, const float* __restrict__ w_temp,
       const float* __restrict__ b_temp)
{
    int bn = blockIdx.x;
    __shared__ float xs[1024];
    __shared__ float part[256];
    int t = threadIdx.x;
    *(float4*)&xs[t * 4] = *(const float4*)(x + (size_t)bn * 1024 + t * 4);
    __syncthreads();
    int j0 = t >> 4, head = t & 15;
    float acc = 0.f;
#pragma unroll 8
    for (int i = 0; i < 64; i++) {
        int j = j0 + (i << 4);
        acc += xs[j] * w_temp[j * 16 + head];
    }
    part[t] = acc;
    __syncthreads();
    if (t < 16) {
        float s = 0.f;
#pragma unroll
        for (int g = 0; g < 16; g++) s += part[g * 16 + t];
        s += b_temp[t];
        float sp = fmaxf(s, 0.f) + log1pf(expf(-fabsf(s)));
        g_T[(size_t)bn * 16 + t] = 0.5f + sp;
    }
}

__global__ void k_zero_norm()
{
    int i = blockIdx.x * 256 + threadIdx.x;
    if (i < cB * cHM) g_norm[i] = 0.f;
}

// ---------------------------------------------------------------------------
// softmax over m (in-place on g_S) + slice_norm accumulation.
// block = 32 rows (b,n); thread t owns hm = 4t..4t+3 (same head group of 16).
// ---------------------------------------------------------------------------
__global__ void __launch_bounds__(256)
k_softmax()
{
    int t   = threadIdx.x;
    int bn0 = blockIdx.x * 32;
    int b   = bn0 / cN;
    float nacc[4] = {0.f, 0.f, 0.f, 0.f};
    int head = t >> 4;
    for (int r = 0; r < 32; r++) {
        size_t bn = (size_t)bn0 + r;
        float4 s = *(float4*)(g_S + bn * 1024 + t * 4);
        float temp  = g_T[bn * 16 + head];
        float inv_t = 1.0f / temp;
        float mx = fmaxf(fmaxf(s.x, s.y), fmaxf(s.z, s.w));
#pragma unroll
        for (int o = 8; o >= 1; o >>= 1)
            mx = fmaxf(mx, __shfl_xor_sync(0xffffffffu, mx, o, 16));
        float4 e;
        e.x = expf((s.x - mx) * inv_t);
        e.y = expf((s.y - mx) * inv_t);
        e.z = expf((s.z - mx) * inv_t);
        e.w = expf((s.w - mx) * inv_t);
        float sum = e.x + e.y + e.z + e.w;
#pragma unroll
        for (int o = 8; o >= 1; o >>= 1)
            sum += __shfl_xor_sync(0xffffffffu, sum, o, 16);
        float inv = 1.0f / sum;
        e.x *= inv; e.y *= inv; e.z *= inv; e.w *= inv;
        *(float4*)(g_S + bn * 1024 + t * 4) = e;
        nacc[0] += e.x; nacc[1] += e.y; nacc[2] += e.z; nacc[3] += e.w;
    }
    float* np = g_norm + b * 1024 + t * 4;
    atomicAdd(np + 0, nacc[0]);
    atomicAdd(np + 1, nacc[1]);
    atomicAdd(np + 2, nacc[2]);
    atomicAdd(np + 3, nacc[3]);
}

// ---------------------------------------------------------------------------
// slice_token: st[m,d] = (y[m,:]@Wv_h[:,d] + norm[m]*bv[d]) / (norm[m]+1e-5)
// one block per (b,h); 64x64 output, K=1024, 4x4 per thread.
// ---------------------------------------------------------------------------
__global__ void __launch_bounds__(256)
k_st(const float* __restrict__ w_kv, const float* __restrict__ b_kv)
{
    int z = blockIdx.x;            // b*16+h
    int b = z >> 4, h = z & 15;
    const float* Yb = g_y + ((size_t)b * 1024 + h * 64) * 1024;
    const float* Wv = w_kv + 1024 + h * 64;
    __shared__ float As[16][64];
    __shared__ float Bs[16][64];
    int t = threadIdx.x;
    int tyy = t >> 4, txx = t & 15;
    float acc[4][4] = {};
    for (int k0 = 0; k0 < 1024; k0 += 16) {
        {
            int m = t >> 2, k4 = (t & 3) << 2;
            float4 v = *(const float4*)(Yb + (size_t)m * 1024 + k0 + k4);
            As[k4 + 0][m] = v.x; As[k4 + 1][m] = v.y;
            As[k4 + 2][m] = v.z; As[k4 + 3][m] = v.w;
        }
        {
            int k = t >> 4, n4 = (t & 15) << 2;
            float4 v = *(const float4*)(Wv + (size_t)(k0 + k) * 2048 + n4);
            *(float4*)&Bs[k][n4] = v;
        }
        __syncthreads();
#pragma unroll
        for (int kk = 0; kk < 16; kk++) {
            float4 a  = *(const float4*)&As[kk][tyy * 4];
            float4 bb = *(const float4*)&Bs[kk][txx * 4];
            float av[4] = {a.x, a.y, a.z, a.w};
            float bv[4] = {bb.x, bb.y, bb.z, bb.w};
#pragma unroll
            for (int i = 0; i < 4; i++)
#pragma unroll
                for (int jj = 0; jj < 4; jj++) acc[i][jj] += av[i] * bv[jj];
        }
        __syncthreads();
    }
#pragma unroll
    for (int i = 0; i < 4; i++) {
        int m = tyy * 4 + i;
        float nrm = g_norm[b * 1024 + h * 64 + m];
        float inv = 1.0f / (nrm + 1e-5f);
#pragma unroll
        for (int jj = 0; jj < 4; jj++) {
            int d = txx * 4 + jj;
            float bvv = b_kv[1024 + h * 64 + d];
            g_st[((size_t)z * 64 + m) * 64 + d] = (acc[i][jj] + nrm * bvv) * inv;
        }
    }
}

// ---------------------------------------------------------------------------
// tiny intra-slice attention: qkv proj + elementwise softmax over d -> ost
// one block per (b,h,m), 64 threads (one per output d).
// ---------------------------------------------------------------------------
__global__ void __launch_bounds__(64)
k_qkv(const float* __restrict__ qkv_proj)
{
    int z = blockIdx.x;               // (b*16+h)*64 + m
    int h = (z >> 6) & 15;
    int d = threadIdx.x;
    __shared__ float st[64];
    __shared__ float ex[64];
    st[d] = g_st[(size_t)z * 64 + d];
    __syncthreads();
    const float* P = qkv_proj + (size_t)h * 64 * 192;
    float q = 0.f, k = 0.f, v = 0.f;
#pragma unroll 8
    for (int j = 0; j < 64; j++) {
        float s = st[j];
        const float* pr = P + j * 192;
        q += s * pr[d];
        k += s * pr[64 + d];
        v += s * pr[128 + d];
    }
    float dot = q * k * 0.125f;       // SCALE = D^-0.5 = 1/8
    ex[d] = dot;
    __syncthreads();
    float mx = -1e30f;
    for (int j = 0; j < 64; j++) mx = fmaxf(mx, ex[j]);
    __syncthreads();
    float e = expf(dot - mx);
    ex[d] = e;
    __syncthreads();
    float sum = 0.f;
    for (int j = 0; j < 64; j++) sum += ex[j];
    g_ost[(size_t)z * 64 + d] = (e / sum) * v;
}

// ---------------------------------------------------------------------------
// Z[b,hm,j] = sum_d ost[b,h,m,d] * w_out[h*64+d, j]
// grid (16 j-chunks, 64 bh), K=64 single shot, 4x4 per thread.
// ---------------------------------------------------------------------------
__global__ void __launch_bounds__(256)
k_zmat(const float* __restrict__ w_out)
{
    int z  = blockIdx.y;              // b*16+h
    int jc = blockIdx.x;              // 0..15
    int b = z >> 4, h = z & 15;
    __shared__ float As[64][64];
    __shared__ float Bs[64][64];
    int t = threadIdx.x;
#pragma unroll
    for (int r = 0; r < 4; r++) {
        int lin = t + r * 256;
        int row = lin >> 4;           // 0..63
        int c4  = (lin & 15) << 2;    // 0..60
        float4 v = *(const float4*)(g_ost + ((size_t)z * 64 + row) * 64 + c4);
        As[c4 + 0][row] = v.x; As[c4 + 1][row] = v.y;
        As[c4 + 2][row] = v.z; As[c4 + 3][row] = v.w;
        float4 w = *(const float4*)(w_out + (size_t)(h * 64 + row) * 1024 + jc * 64 + c4);
        *(float4*)&Bs[row][c4] = w;
    }
    __syncthreads();
    int tyy = t >> 4, txx = t & 15;
    float acc[4][4] = {};
#pragma unroll
    for (int kk = 0; kk < 64; kk++) {
        float4 a  = *(const float4*)&As[kk][tyy * 4];
        float4 bb = *(const float4*)&Bs[kk][txx * 4];
        float av[4] = {a.x, a.y, a.z, a.w};
        float bv[4] = {bb.x, bb.y, bb.z, bb.w};
#pragma unroll
        for (int i = 0; i < 4; i++)
#pragma unroll
            for (int jj = 0; jj < 4; jj++) acc[i][jj] += av[i] * bv[jj];
    }
#pragma unroll
    for (int i = 0; i < 4; i++)
#pragma unroll
        for (int jj = 0; jj < 4; jj++)
            g_Z[((size_t)b * 1024 + h * 64 + tyy * 4 + i) * 1024 + jc * 64 + txx * 4 + jj]
                = acc[i][jj];
}

// ---------------------------------------------------------------------------
extern "C" void kernel_launch(void* const* d_in, const int* in_sizes, int n_in,
                              void* d_out, int out_size)
{
    (void)in_sizes; (void)n_in; (void)out_size;
    const float* x      = (const float*)d_in[0];
    // d_in[1] = c : unused by the reference
    const float* w_kv   = (const float*)d_in[2];
    const float* b_kv   = (const float*)d_in[3];
    const float* w_temp = (const float*)d_in[4];
    const float* b_temp = (const float*)d_in[5];
    const float* xq     = (const float*)d_in[6];
    const float* qkv_p  = (const float*)d_in[7];
    const float* w_out  = (const float*)d_in[8];
    const float* b_out  = (const float*)d_in[9];
    float* out = (float*)d_out;

    float *pS, *pAt, *pc, *py, *pZ;
    cudaGetSymbolAddress((void**)&pS,  g_S);
    cudaGetSymbolAddress((void**)&pAt, g_At);
    cudaGetSymbolAddress((void**)&pc,  g_c);
    cudaGetSymbolAddress((void**)&py,  g_y);
    cudaGetSymbolAddress((void**)&pZ,  g_Z);

    // 1. head-projection precompute
    k_prep<<<4096, 256>>>(xq, w_kv, b_kv);
    // 2. temperatures
    k_temp<<<cB * cN, 256>>>(x, w_temp, b_temp);
    // 3. scores: S[bn,hm] = x @ At + c   (M=32768,N=1024,K=1024)
    sgemm_kernel<false, true><<<dim3(8, 256, 1), 256>>>(
        x, pAt, pS, pc, cB * cN, cHM, cH, 1024, 1024, 1024, 0, 0, 0);
    // 4. zero norms, softmax over m + norm accumulation
    k_zero_norm<<<16, 256>>>();
    k_softmax<<<(cB * cN) / 32, 256>>>();
    // 5. y = w^T x per batch  (M=1024,N=1024,K=8192)
    sgemm_kernel<true, false><<<dim3(8, 8, cB), 256>>>(
        pS, x, py, nullptr, cHM, cH, cN, 1024, 1024, 1024,
        (long long)cN * cHM, (long long)cN * cH, (long long)cHM * cH);
    // 6. slice_token
    k_st<<<cB * cNH, 256>>>(w_kv, b_kv);
    // 7. tiny qkv + elementwise attention
    k_qkv<<<cB * cNH * cM, 64>>>(qkv_p);
    // 8. Z = ost @ w_out_h
    k_zmat<<<dim3(16, cB * cNH), 256>>>(w_out);
    // 9. out = w @ Z + b_out per batch  (M=8192,N=1024,K=1024)
    sgemm_kernel<false, true><<<dim3(8, 64, cB), 256>>>(
        pS, pZ, out, b_out, cN, cH, cHM, 1024, 1024, 1024,
        (long long)cN * cHM, (long long)cHM * cH, (long long)cN * cH);
}

// round 5
// speedup vs baseline: 1.9955x; 1.9932x over previous
#include <cuda_runtime.h>
#include <cuda_bf16.h>
#include <math.h>
#include <stdint.h>

constexpr int cB = 4, cN = 8192, cH = 1024, cNH = 16, cHM = 1024;

// ---------------- scratch (device globals) ----------------
__device__ float g_S [(size_t)cB * cN * cHM];
__device__ __nv_bfloat16 g_xh [(size_t)cB * cN * cH];
__device__ __nv_bfloat16 g_xl [(size_t)cB * cN * cH];
__device__ __nv_bfloat16 g_xth[(size_t)cB * cH * cN];
__device__ __nv_bfloat16 g_xtl[(size_t)cB * cH * cN];
__device__ __nv_bfloat16 g_Sh [(size_t)cB * cN * cHM];
__device__ __nv_bfloat16 g_Sl [(size_t)cB * cN * cHM];
__device__ __nv_bfloat16 g_Sth[(size_t)cB * cHM * cN];
__device__ __nv_bfloat16 g_Stl[(size_t)cB * cHM * cN];
__device__ __nv_bfloat16 g_Ath[cHM * cH];
__device__ __nv_bfloat16 g_Atl[cHM * cH];
__device__ __nv_bfloat16 g_Zth[(size_t)cB * cH * cHM];
__device__ __nv_bfloat16 g_Ztl[(size_t)cB * cH * cHM];
__device__ float g_c[cHM];
__device__ float g_T[cB * cN * cNH];
__device__ float g_norm[cB * cHM];
__device__ float g_y[(size_t)cB * cHM * cH];
__device__ float g_st[cB * cNH * 64 * 64];
__device__ float g_ost[cB * cNH * 64 * 64];

// ---------------- helpers ----------------
__device__ __forceinline__ uint32_t smem_u32(const void* p) {
    uint32_t a;
    asm("{ .reg .u64 t; cvta.to.shared.u64 t, %1; cvt.u32.u64 %0, t; }" : "=r"(a) : "l"(p));
    return a;
}
__device__ __forceinline__ void cp16(uint32_t s, const void* g) {
    asm volatile("cp.async.cg.shared.global [%0], [%1], 16;" :: "r"(s), "l"(g));
}
#define CP_COMMIT() asm volatile("cp.async.commit_group;" ::: "memory")
#define CP_WAIT1()  asm volatile("cp.async.wait_group 1;" ::: "memory")
#define CP_WAIT0()  asm volatile("cp.async.wait_group 0;" ::: "memory")

__device__ __forceinline__ void ldsm4(uint32_t* r, uint32_t a) {
    asm volatile("ldmatrix.sync.aligned.m8n8.x4.shared.b16 {%0,%1,%2,%3}, [%4];"
        : "=r"(r[0]), "=r"(r[1]), "=r"(r[2]), "=r"(r[3]) : "r"(a));
}
__device__ __forceinline__ void mma16816(float* d, const uint32_t* a,
                                         uint32_t b0, uint32_t b1) {
    asm volatile("mma.sync.aligned.m16n8k16.row.col.f32.bf16.bf16.f32 "
        "{%0,%1,%2,%3}, {%4,%5,%6,%7}, {%8,%9}, {%0,%1,%2,%3};"
        : "+f"(d[0]), "+f"(d[1]), "+f"(d[2]), "+f"(d[3])
        : "r"(a[0]), "r"(a[1]), "r"(a[2]), "r"(a[3]), "r"(b0), "r"(b1));
}
__device__ __forceinline__ void split2(float v, __nv_bfloat16& h, __nv_bfloat16& l) {
    h = __float2bfloat16(v);
    l = __float2bfloat16(v - __bfloat162float(h));
}

// ============ HMMA split-bf16 GEMM: C[m][n] = sum_k A[m][k]*B[n][k] ==========
// CTA tile 128x128, 8 warps (2x4), warp tile 64x32, Kc=64 double-buffered.
constexpr int T_AH = 0, T_AL = 16384, T_BH = 32768, T_BL = 49152;
constexpr int BUFB = 65536;
constexpr int GSMEM = 2 * BUFB;   // 128 KB

template<bool HAS_BIAS>
__global__ void __launch_bounds__(256, 1)
mma_gemm(const __nv_bfloat16* __restrict__ Ah, const __nv_bfloat16* __restrict__ Al,
         const __nv_bfloat16* __restrict__ Bh, const __nv_bfloat16* __restrict__ Bl,
         float* __restrict__ C, const float* __restrict__ bias,
         int Kdim, int lda, int ldb, int ldc,
         long long sA, long long sB, long long sC)
{
    extern __shared__ __align__(128) char smem[];
    const int tid = threadIdx.x, wid = tid >> 5, lane = tid & 31;
    uint32_t sbase = smem_u32(smem);
    const long long z = blockIdx.z;
    Ah += z * sA; Al += z * sA; Bh += z * sB; Bl += z * sB; C += z * sC;
    const int m0 = blockIdx.y * 128, n0 = blockIdx.x * 128;

    auto issue = [&](int c) {
        const int kc = c << 6;
        uint32_t sb = sbase + (c & 1) * BUFB;
#pragma unroll
        for (int i = 0; i < 16; i++) {
            const int tile = i >> 2;                 // uniform per i
            const int idx  = ((i & 3) << 8) + tid;   // 0..1023
            const int row  = idx >> 3, seg = idx & 7;
            uint32_t so = sb + tile * 16384 + row * 128 + ((seg ^ (row & 7)) << 4);
            const __nv_bfloat16* gp;
            if (tile == 0)      gp = Ah + (long long)(m0 + row) * lda + kc + seg * 8;
            else if (tile == 1) gp = Al + (long long)(m0 + row) * lda + kc + seg * 8;
            else if (tile == 2) gp = Bh + (long long)(n0 + row) * ldb + kc + seg * 8;
            else                gp = Bl + (long long)(n0 + row) * ldb + kc + seg * 8;
            cp16(so, gp);
        }
        CP_COMMIT();
    };

    const int NC = Kdim >> 6;
    issue(0);

    const int wm = (wid >> 2) * 64, wn = (wid & 3) * 32;
    const int arow  = wm + (lane & 15);
    const int akseg = lane >> 4;
    const int r7a   = arow & 7;
    const int brow  = wn + ((lane >> 4) << 3) + (lane & 7);
    const int bkseg = (lane >> 3) & 1;
    const int r7b   = brow & 7;

    float acc[4][4][4];
#pragma unroll
    for (int a = 0; a < 4; a++)
#pragma unroll
        for (int b = 0; b < 4; b++)
#pragma unroll
            for (int q = 0; q < 4; q++) acc[a][b][q] = 0.f;

    for (int c = 0; c < NC; c++) {
        if (c + 1 < NC) { issue(c + 1); CP_WAIT1(); } else { CP_WAIT0(); }
        __syncthreads();
        uint32_t sb = sbase + (c & 1) * BUFB;
#pragma unroll
        for (int ks = 0; ks < 4; ks++) {
            const int ks2 = ks * 2;
            uint32_t ah[4][4], alr[4][4], bh[2][4], bl[2][4];
#pragma unroll
            for (int mt = 0; mt < 4; mt++) {
                uint32_t ao = sb + T_AH + (arow + mt * 16) * 128
                            + (uint32_t)((((ks2 + akseg) ^ r7a)) << 4);
                ldsm4(ah[mt], ao);
                ldsm4(alr[mt], ao + (T_AL - T_AH));
            }
#pragma unroll
            for (int np = 0; np < 2; np++) {
                uint32_t bo = sb + T_BH + (brow + np * 16) * 128
                            + (uint32_t)((((ks2 + bkseg) ^ r7b)) << 4);
                ldsm4(bh[np], bo);
                ldsm4(bl[np], bo + (T_BL - T_BH));
            }
#pragma unroll
            for (int mt = 0; mt < 4; mt++)
#pragma unroll
                for (int nt = 0; nt < 4; nt++) {
                    const int np = nt >> 1, hb = (nt & 1) * 2;
                    mma16816(acc[mt][nt], ah[mt],  bh[np][hb], bh[np][hb + 1]);
                    mma16816(acc[mt][nt], ah[mt],  bl[np][hb], bl[np][hb + 1]);
                    mma16816(acc[mt][nt], alr[mt], bh[np][hb], bh[np][hb + 1]);
                }
        }
        __syncthreads();
    }

    const int rr = lane >> 2, cc = (lane & 3) * 2;
#pragma unroll
    for (int mt = 0; mt < 4; mt++) {
        const long long m = m0 + wm + mt * 16 + rr;
#pragma unroll
        for (int nt = 0; nt < 4; nt++) {
            const int n = n0 + wn + nt * 8 + cc;
            float bx = 0.f, by = 0.f;
            if (HAS_BIAS) {
                float2 b2 = *(const float2*)(bias + n);
                bx = b2.x; by = b2.y;
            }
            float2 v0 = make_float2(acc[mt][nt][0] + bx, acc[mt][nt][1] + by);
            float2 v1 = make_float2(acc[mt][nt][2] + bx, acc[mt][nt][3] + by);
            *(float2*)(C + m * ldc + n)       = v0;
            *(float2*)(C + (m + 8) * ldc + n) = v1;
        }
    }
}

// ============ aux kernels ============
__global__ void __launch_bounds__(256)
k_prep(const float* __restrict__ xq, const float* __restrict__ w_kv,
       const float* __restrict__ b_kv)
{
    int idx = blockIdx.x * 256 + threadIdx.x;
    int j = idx >> 10, hm = idx & 1023;
    int hbase = (hm >> 6) << 6;
    const float* xr = xq + (size_t)hm * 64;
    const float* wr = w_kv + (size_t)j * 2048 + hbase;
    float acc = 0.f;
#pragma unroll 8
    for (int d = 0; d < 64; d++) acc += xr[d] * wr[d];
    __nv_bfloat16 h, l; split2(acc, h, l);
    g_Ath[(size_t)hm * 1024 + j] = h;
    g_Atl[(size_t)hm * 1024 + j] = l;
    if (j == 0) {
        const float* br = b_kv + hbase;
        float cc = 0.f;
        for (int d = 0; d < 64; d++) cc += xr[d] * br[d];
        g_c[hm] = cc;
    }
}

__global__ void __launch_bounds__(256)
k_convx(const float* __restrict__ x)
{
    __shared__ __nv_bfloat16 sh[64][72];
    __shared__ __nv_bfloat16 sl[64][72];
    int jt = blockIdx.x, nt = blockIdx.y;
    int t = threadIdx.x;
    int r = t >> 2, c0 = (t & 3) * 16;
    size_t bn = (size_t)nt * 64 + r;
    const float* xr = x + bn * 1024 + jt * 64 + c0;
    __nv_bfloat16* dh = g_xh + bn * 1024 + jt * 64 + c0;
    __nv_bfloat16* dl = g_xl + bn * 1024 + jt * 64 + c0;
#pragma unroll
    for (int i = 0; i < 16; i += 2) {
        float2 v = *(const float2*)(xr + i);
        __nv_bfloat16 h0, l0, h1, l1;
        split2(v.x, h0, l0); split2(v.y, h1, l1);
        *(__nv_bfloat162*)(dh + i) = __nv_bfloat162(h0, h1);
        *(__nv_bfloat162*)(dl + i) = __nv_bfloat162(l0, l1);
        sh[r][c0 + i] = h0; sh[r][c0 + i + 1] = h1;
        sl[r][c0 + i] = l0; sl[r][c0 + i + 1] = l1;
    }
    __syncthreads();
    int b = (nt * 64) >> 13, nn0 = (nt * 64) & 8191;
    __nv_bfloat16* th = g_xth + ((size_t)(b * 1024 + jt * 64 + r)) * 8192 + nn0 + c0;
    __nv_bfloat16* tl = g_xtl + ((size_t)(b * 1024 + jt * 64 + r)) * 8192 + nn0 + c0;
#pragma unroll
    for (int i = 0; i < 16; i += 2) {
        *(__nv_bfloat162*)(th + i) = __nv_bfloat162(sh[c0 + i][r], sh[c0 + i + 1][r]);
        *(__nv_bfloat162*)(tl + i) = __nv_bfloat162(sl[c0 + i][r], sl[c0 + i + 1][r]);
    }
}

__global__ void __launch_bounds__(256)
k_temp(const float* __restrict__ x, const float* __restrict__ w_temp,
       const float* __restrict__ b_temp)
{
    int bn = blockIdx.x;
    __shared__ float xs[1024];
    __shared__ float part[256];
    int t = threadIdx.x;
    *(float4*)&xs[t * 4] = *(const float4*)(x + (size_t)bn * 1024 + t * 4);
    __syncthreads();
    int j0 = t >> 4, head = t & 15;
    float acc = 0.f;
#pragma unroll 8
    for (int i = 0; i < 64; i++) {
        int j = j0 + (i << 4);
        acc += xs[j] * w_temp[j * 16 + head];
    }
    part[t] = acc;
    __syncthreads();
    if (t < 16) {
        float s = 0.f;
#pragma unroll
        for (int g = 0; g < 16; g++) s += part[g * 16 + t];
        s += b_temp[t];
        float sp = fmaxf(s, 0.f) + log1pf(expf(-fabsf(s)));
        g_T[(size_t)bn * 16 + t] = 0.5f + sp;
    }
}

__global__ void k_zero_norm()
{
    int i = blockIdx.x * 256 + threadIdx.x;
    if (i < cB * cHM) g_norm[i] = 0.f;
}

__global__ void __launch_bounds__(256)
k_softmax()
{
    int t = threadIdx.x;
    int bn0 = blockIdx.x * 32;
    int b = bn0 / cN;
    float nacc[4] = {0.f, 0.f, 0.f, 0.f};
    int head = t >> 4;
    for (int r = 0; r < 32; r++) {
        size_t bn = (size_t)bn0 + r;
        float4 s = *(float4*)(g_S + bn * 1024 + t * 4);
        float inv_t = 1.0f / g_T[bn * 16 + head];
        float mx = fmaxf(fmaxf(s.x, s.y), fmaxf(s.z, s.w));
#pragma unroll
        for (int o = 8; o >= 1; o >>= 1)
            mx = fmaxf(mx, __shfl_xor_sync(0xffffffffu, mx, o, 16));
        float4 e;
        e.x = expf((s.x - mx) * inv_t); e.y = expf((s.y - mx) * inv_t);
        e.z = expf((s.z - mx) * inv_t); e.w = expf((s.w - mx) * inv_t);
        float sum = e.x + e.y + e.z + e.w;
#pragma unroll
        for (int o = 8; o >= 1; o >>= 1)
            sum += __shfl_xor_sync(0xffffffffu, sum, o, 16);
        float inv = 1.0f / sum;
        e.x *= inv; e.y *= inv; e.z *= inv; e.w *= inv;
        __nv_bfloat16 h0, l0, h1, l1, h2, l2, h3, l3;
        split2(e.x, h0, l0); split2(e.y, h1, l1);
        split2(e.z, h2, l2); split2(e.w, h3, l3);
        __nv_bfloat16* ph = g_Sh + bn * 1024 + t * 4;
        __nv_bfloat16* pl = g_Sl + bn * 1024 + t * 4;
        *(__nv_bfloat162*)(ph)     = __nv_bfloat162(h0, h1);
        *(__nv_bfloat162*)(ph + 2) = __nv_bfloat162(h2, h3);
        *(__nv_bfloat162*)(pl)     = __nv_bfloat162(l0, l1);
        *(__nv_bfloat162*)(pl + 2) = __nv_bfloat162(l2, l3);
        nacc[0] += e.x; nacc[1] += e.y; nacc[2] += e.z; nacc[3] += e.w;
    }
    float* np = g_norm + b * 1024 + t * 4;
    atomicAdd(np + 0, nacc[0]); atomicAdd(np + 1, nacc[1]);
    atomicAdd(np + 2, nacc[2]); atomicAdd(np + 3, nacc[3]);
}

__global__ void __launch_bounds__(256)
k_transS()
{
    __shared__ __nv_bfloat16 sh[64][72];
    __shared__ __nv_bfloat16 sl[64][72];
    int ht = blockIdx.x, nt = blockIdx.y;
    int t = threadIdx.x;
    int r = t >> 2, c0 = (t & 3) * 16;
    size_t bn = (size_t)nt * 64 + r;
    const uint4* srch = (const uint4*)(g_Sh + bn * 1024 + ht * 64 + c0);
    const uint4* srcl = (const uint4*)(g_Sl + bn * 1024 + ht * 64 + c0);
    *(uint4*)(&sh[r][c0])     = srch[0];
    *(uint4*)(&sh[r][c0 + 8]) = srch[1];
    *(uint4*)(&sl[r][c0])     = srcl[0];
    *(uint4*)(&sl[r][c0 + 8]) = srcl[1];
    __syncthreads();
    int b = (nt * 64) >> 13, nn0 = (nt * 64) & 8191;
    __nv_bfloat16* th = g_Sth + ((size_t)(b * 1024 + ht * 64 + r)) * 8192 + nn0 + c0;
    __nv_bfloat16* tl = g_Stl + ((size_t)(b * 1024 + ht * 64 + r)) * 8192 + nn0 + c0;
#pragma unroll
    for (int i = 0; i < 16; i += 2) {
        *(__nv_bfloat162*)(th + i) = __nv_bfloat162(sh[c0 + i][r], sh[c0 + i + 1][r]);
        *(__nv_bfloat162*)(tl + i) = __nv_bfloat162(sl[c0 + i][r], sl[c0 + i + 1][r]);
    }
}

__global__ void __launch_bounds__(256)
k_st(const float* __restrict__ w_kv, const float* __restrict__ b_kv)
{
    int z = blockIdx.x;
    int b = z >> 4, h = z & 15;
    const float* Yb = g_y + ((size_t)b * 1024 + h * 64) * 1024;
    const float* Wv = w_kv + 1024 + h * 64;
    __shared__ float As[16][64];
    __shared__ float Bs[16][64];
    int t = threadIdx.x;
    int tyy = t >> 4, txx = t & 15;
    float acc[4][4] = {};
    for (int k0 = 0; k0 < 1024; k0 += 16) {
        {
            int m = t >> 2, k4 = (t & 3) << 2;
            float4 v = *(const float4*)(Yb + (size_t)m * 1024 + k0 + k4);
            As[k4 + 0][m] = v.x; As[k4 + 1][m] = v.y;
            As[k4 + 2][m] = v.z; As[k4 + 3][m] = v.w;
        }
        {
            int k = t >> 4, n4 = (t & 15) << 2;
            *(float4*)&Bs[k][n4] = *(const float4*)(Wv + (size_t)(k0 + k) * 2048 + n4);
        }
        __syncthreads();
#pragma unroll
        for (int kk = 0; kk < 16; kk++) {
            float4 a  = *(const float4*)&As[kk][tyy * 4];
            float4 bb = *(const float4*)&Bs[kk][txx * 4];
            float av[4] = {a.x, a.y, a.z, a.w};
            float bv[4] = {bb.x, bb.y, bb.z, bb.w};
#pragma unroll
            for (int i = 0; i < 4; i++)
#pragma unroll
                for (int jj = 0; jj < 4; jj++) acc[i][jj] += av[i] * bv[jj];
        }
        __syncthreads();
    }
#pragma unroll
    for (int i = 0; i < 4; i++) {
        int m = tyy * 4 + i;
        float nrm = g_norm[b * 1024 + h * 64 + m];
        float inv = 1.0f / (nrm + 1e-5f);
#pragma unroll
        for (int jj = 0; jj < 4; jj++) {
            int d = txx * 4 + jj;
            float bvv = b_kv[1024 + h * 64 + d];
            g_st[((size_t)z * 64 + m) * 64 + d] = (acc[i][jj] + nrm * bvv) * inv;
        }
    }
}

__global__ void __launch_bounds__(64)
k_qkv(const float* __restrict__ qkv_proj)
{
    int z = blockIdx.x;
    int h = (z >> 6) & 15;
    int d = threadIdx.x;
    __shared__ float st[64];
    __shared__ float ex[64];
    st[d] = g_st[(size_t)z * 64 + d];
    __syncthreads();
    const float* P = qkv_proj + (size_t)h * 64 * 192;
    float q = 0.f, k = 0.f, v = 0.f;
#pragma unroll 8
    for (int j = 0; j < 64; j++) {
        float s = st[j];
        const float* pr = P + j * 192;
        q += s * pr[d]; k += s * pr[64 + d]; v += s * pr[128 + d];
    }
    float dot = q * k * 0.125f;
    ex[d] = dot;
    __syncthreads();
    float mx = -1e30f;
    for (int j = 0; j < 64; j++) mx = fmaxf(mx, ex[j]);
    __syncthreads();
    float e = expf(dot - mx);
    ex[d] = e;
    __syncthreads();
    float sum = 0.f;
    for (int j = 0; j < 64; j++) sum += ex[j];
    g_ost[(size_t)z * 64 + d] = (e / sum) * v;
}

__global__ void __launch_bounds__(256)
k_zmat(const float* __restrict__ w_out)
{
    int z = blockIdx.y, jc = blockIdx.x;
    int b = z >> 4, h = z & 15;
    __shared__ float As[64][64];
    __shared__ float Bs[64][64];
    int t = threadIdx.x;
#pragma unroll
    for (int r = 0; r < 4; r++) {
        int lin = t + r * 256;
        int row = lin >> 4;
        int c4  = (lin & 15) << 2;
        float4 v = *(const float4*)(g_ost + ((size_t)z * 64 + row) * 64 + c4);
        As[c4 + 0][row] = v.x; As[c4 + 1][row] = v.y;
        As[c4 + 2][row] = v.z; As[c4 + 3][row] = v.w;
        *(float4*)&Bs[row][c4] =
            *(const float4*)(w_out + (size_t)(h * 64 + row) * 1024 + jc * 64 + c4);
    }
    __syncthreads();
    int tyy = t >> 4, txx = t & 15;
    float acc[4][4] = {};
#pragma unroll
    for (int kk = 0; kk < 64; kk++) {
        float4 a  = *(const float4*)&As[kk][tyy * 4];
        float4 bb = *(const float4*)&Bs[kk][txx * 4];
        float av[4] = {a.x, a.y, a.z, a.w};
        float bv[4] = {bb.x, bb.y, bb.z, bb.w};
#pragma unroll
        for (int i = 0; i < 4; i++)
#pragma unroll
            for (int jj = 0; jj < 4; jj++) acc[i][jj] += av[i] * bv[jj];
    }
#pragma unroll
    for (int i = 0; i < 4; i++) {
        int hm = h * 64 + tyy * 4 + i;
#pragma unroll
        for (int jj = 0; jj < 4; jj++) {
            int j = jc * 64 + txx * 4 + jj;
            __nv_bfloat16 hh, ll; split2(acc[i][jj], hh, ll);
            size_t o = ((size_t)b * 1024 + j) * 1024 + hm;
            g_Zth[o] = hh; g_Ztl[o] = ll;
        }
    }
}

// ---------------------------------------------------------------------------
extern "C" void kernel_launch(void* const* d_in, const int* in_sizes, int n_in,
                              void* d_out, int out_size)
{
    (void)in_sizes; (void)n_in; (void)out_size;
    const float* x      = (const float*)d_in[0];
    const float* w_kv   = (const float*)d_in[2];
    const float* b_kv   = (const float*)d_in[3];
    const float* w_temp = (const float*)d_in[4];
    const float* b_temp = (const float*)d_in[5];
    const float* xq     = (const float*)d_in[6];
    const float* qkv_p  = (const float*)d_in[7];
    const float* w_out  = (const float*)d_in[8];
    const float* b_out  = (const float*)d_in[9];
    float* out = (float*)d_out;

    float *pS, *pc;
    __nv_bfloat16 *pxh, *pxl, *pxth, *pxtl, *pSh, *pSl, *pSth, *pStl, *pAth, *pAtl, *pZth, *pZtl;
    cudaGetSymbolAddress((void**)&pS,  g_S);
    cudaGetSymbolAddress((void**)&pc,  g_c);
    cudaGetSymbolAddress((void**)&pxh, g_xh);   cudaGetSymbolAddress((void**)&pxl, g_xl);
    cudaGetSymbolAddress((void**)&pxth, g_xth); cudaGetSymbolAddress((void**)&pxtl, g_xtl);
    cudaGetSymbolAddress((void**)&pSh, g_Sh);   cudaGetSymbolAddress((void**)&pSl, g_Sl);
    cudaGetSymbolAddress((void**)&pSth, g_Sth); cudaGetSymbolAddress((void**)&pStl, g_Stl);
    cudaGetSymbolAddress((void**)&pAth, g_Ath); cudaGetSymbolAddress((void**)&pAtl, g_Atl);
    cudaGetSymbolAddress((void**)&pZth, g_Zth); cudaGetSymbolAddress((void**)&pZtl, g_Ztl);
    float* py; cudaGetSymbolAddress((void**)&py, g_y);

    cudaFuncSetAttribute(mma_gemm<true>,  cudaFuncAttributeMaxDynamicSharedMemorySize, GSMEM);
    cudaFuncSetAttribute(mma_gemm<false>, cudaFuncAttributeMaxDynamicSharedMemorySize, GSMEM);

    k_prep<<<4096, 256>>>(xq, w_kv, b_kv);
    k_convx<<<dim3(16, 512), 256>>>(x);
    k_temp<<<cB * cN, 256>>>(x, w_temp, b_temp);
    // scores: S = x @ At^T + c   (M=32768, N=1024, K=1024)
    mma_gemm<true><<<dim3(8, 256, 1), 256, GSMEM>>>(
        pxh, pxl, pAth, pAtl, pS, pc, 1024, 1024, 1024, 1024, 0, 0, 0);
    k_zero_norm<<<16, 256>>>();
    k_softmax<<<(cB * cN) / 32, 256>>>();
    k_transS<<<dim3(16, 512), 256>>>();
    // y[b] = S[b]^T @ x[b]  (M=1024, N=1024, K=8192)
    mma_gemm<false><<<dim3(8, 8, cB), 256, GSMEM>>>(
        pSth, pStl, pxth, pxtl, py, nullptr, 8192, 8192, 8192, 1024,
        (long long)cHM * cN, (long long)cH * cN, (long long)cHM * cH);
    k_st<<<cB * cNH, 256>>>(w_kv, b_kv);
    k_qkv<<<cB * cNH * 64, 64>>>(qkv_p);
    k_zmat<<<dim3(16, cB * cNH), 256>>>(w_out);
    // out[b] = S[b] @ Zt[b]^T + b_out  (M=8192, N=1024, K=1024)
    mma_gemm<true><<<dim3(8, 64, cB), 256, GSMEM>>>(
        pSh, pSl, pZth, pZtl, out, b_out, 1024, 1024, 1024, 1024,
        (long long)cN * cHM, (long long)cH * cHM, (long long)cN * cH);
}

// round 6
// speedup vs baseline: 2.1282x; 1.0665x over previous
#include <cuda_runtime.h>
#include <cuda_bf16.h>
#include <math.h>
#include <stdint.h>

constexpr int cB = 4, cN = 8192, cH = 1024, cNH = 16, cHM = 1024;

// ---------------- scratch (device globals) ----------------
__device__ __nv_bfloat16 g_xh [(size_t)cB * cN * cH];
__device__ __nv_bfloat16 g_xl [(size_t)cB * cN * cH];
__device__ __nv_bfloat16 g_xth[(size_t)cB * cH * cN];
__device__ __nv_bfloat16 g_xtl[(size_t)cB * cH * cN];
__device__ __nv_bfloat16 g_Sh [(size_t)cB * cN * cHM];
__device__ __nv_bfloat16 g_Sl [(size_t)cB * cN * cHM];
__device__ __nv_bfloat16 g_Sth[(size_t)cB * cHM * cN];
__device__ __nv_bfloat16 g_Stl[(size_t)cB * cHM * cN];
__device__ __nv_bfloat16 g_Ath[cHM * cH];
__device__ __nv_bfloat16 g_Atl[cHM * cH];
__device__ __nv_bfloat16 g_Zth[(size_t)cB * cH * cHM];
__device__ __nv_bfloat16 g_Ztl[(size_t)cB * cH * cHM];
__device__ float g_c[cHM];
__device__ float g_T[cB * cN * cNH];
__device__ float g_norm[cB * cHM];
__device__ float g_y[(size_t)cB * cHM * cH];
__device__ float g_st[cB * cNH * 64 * 64];
__device__ float g_ost[cB * cNH * 64 * 64];

// ---------------- helpers ----------------
__device__ __forceinline__ uint32_t smem_u32(const void* p) {
    uint32_t a;
    asm("{ .reg .u64 t; cvta.to.shared.u64 t, %1; cvt.u32.u64 %0, t; }" : "=r"(a) : "l"(p));
    return a;
}
__device__ __forceinline__ void cp16(uint32_t s, const void* g) {
    asm volatile("cp.async.cg.shared.global [%0], [%1], 16;" :: "r"(s), "l"(g));
}
#define CP_COMMIT() asm volatile("cp.async.commit_group;" ::: "memory")
#define CP_WAIT1()  asm volatile("cp.async.wait_group 1;" ::: "memory")
#define CP_WAIT0()  asm volatile("cp.async.wait_group 0;" ::: "memory")

__device__ __forceinline__ void ldsm4(uint32_t* r, uint32_t a) {
    asm volatile("ldmatrix.sync.aligned.m8n8.x4.shared.b16 {%0,%1,%2,%3}, [%4];"
        : "=r"(r[0]), "=r"(r[1]), "=r"(r[2]), "=r"(r[3]) : "r"(a));
}
__device__ __forceinline__ void mma16816(float* d, const uint32_t* a,
                                         uint32_t b0, uint32_t b1) {
    asm volatile("mma.sync.aligned.m16n8k16.row.col.f32.bf16.bf16.f32 "
        "{%0,%1,%2,%3}, {%4,%5,%6,%7}, {%8,%9}, {%0,%1,%2,%3};"
        : "+f"(d[0]), "+f"(d[1]), "+f"(d[2]), "+f"(d[3])
        : "r"(a[0]), "r"(a[1]), "r"(a[2]), "r"(a[3]), "r"(b0), "r"(b1));
}
__device__ __forceinline__ void split2(float v, __nv_bfloat16& h, __nv_bfloat16& l) {
    h = __float2bfloat16(v);
    l = __float2bfloat16(v - __bfloat162float(h));
}

// ============ HMMA split-bf16 GEMM: C[m][n] = sum_k A[m][k]*B[n][k] ==========
// CTA tile 128x128, 8 warps (2x4), warp tile 64x32, Kc=64 double-buffered.
// EPI: 1 = bias + store, 2 = atomicAdd accumulate, 3 = fused softmax epilogue.
constexpr int T_AH = 0, T_AL = 16384, T_BH = 32768, T_BL = 49152;
constexpr int BUFB = 65536;
constexpr int GSMEM = 2 * BUFB;   // 128 KB

template<int EPI>
__global__ void __launch_bounds__(256, 1)
mma_gemm(const __nv_bfloat16* __restrict__ Ah, const __nv_bfloat16* __restrict__ Al,
         const __nv_bfloat16* __restrict__ Bh, const __nv_bfloat16* __restrict__ Bl,
         float* __restrict__ C, const float* __restrict__ bias,
         int Kdim, int lda, int ldb, int ldc,
         long long sA, long long sB, long long sC, int ksl)
{
    extern __shared__ __align__(128) char smem[];
    const int tid = threadIdx.x, wid = tid >> 5, lane = tid & 31;
    uint32_t sbase = smem_u32(smem);
    const long long zz = blockIdx.z;
    const long long batch = zz >> ksl;
    const long long kidx = zz & ((1 << ksl) - 1);
    Ah += batch * sA + kidx * (long long)Kdim;
    Al += batch * sA + kidx * (long long)Kdim;
    Bh += batch * sB + kidx * (long long)Kdim;
    Bl += batch * sB + kidx * (long long)Kdim;
    C  += batch * sC;
    const int m0 = blockIdx.y * 128, n0 = blockIdx.x * 128;

    auto issue = [&](int c) {
        const int kc = c << 6;
        uint32_t sb = sbase + (c & 1) * BUFB;
#pragma unroll
        for (int i = 0; i < 16; i++) {
            const int tile = i >> 2;
            const int idx  = ((i & 3) << 8) + tid;
            const int row  = idx >> 3, seg = idx & 7;
            uint32_t so = sb + tile * 16384 + row * 128 + ((seg ^ (row & 7)) << 4);
            const __nv_bfloat16* gp;
            if (tile == 0)      gp = Ah + (long long)(m0 + row) * lda + kc + seg * 8;
            else if (tile == 1) gp = Al + (long long)(m0 + row) * lda + kc + seg * 8;
            else if (tile == 2) gp = Bh + (long long)(n0 + row) * ldb + kc + seg * 8;
            else                gp = Bl + (long long)(n0 + row) * ldb + kc + seg * 8;
            cp16(so, gp);
        }
        CP_COMMIT();
    };

    const int NC = Kdim >> 6;
    issue(0);

    const int wm = (wid >> 2) * 64, wn = (wid & 3) * 32;
    const int arow  = wm + (lane & 15);
    const int akseg = lane >> 4;
    const int r7a   = arow & 7;
    const int brow  = wn + ((lane >> 4) << 3) + (lane & 7);
    const int bkseg = (lane >> 3) & 1;
    const int r7b   = brow & 7;

    float acc[4][4][4];
#pragma unroll
    for (int a = 0; a < 4; a++)
#pragma unroll
        for (int b = 0; b < 4; b++)
#pragma unroll
            for (int q = 0; q < 4; q++) acc[a][b][q] = 0.f;

    for (int c = 0; c < NC; c++) {
        if (c + 1 < NC) { issue(c + 1); CP_WAIT1(); } else { CP_WAIT0(); }
        __syncthreads();
        uint32_t sb = sbase + (c & 1) * BUFB;
#pragma unroll
        for (int ks = 0; ks < 4; ks++) {
            const int ks2 = ks * 2;
            uint32_t ah[4][4], alr[4][4], bh[2][4], bl[2][4];
#pragma unroll
            for (int mt = 0; mt < 4; mt++) {
                uint32_t ao = sb + T_AH + (arow + mt * 16) * 128
                            + (uint32_t)((((ks2 + akseg) ^ r7a)) << 4);
                ldsm4(ah[mt], ao);
                ldsm4(alr[mt], ao + (T_AL - T_AH));
            }
#pragma unroll
            for (int np = 0; np < 2; np++) {
                uint32_t bo = sb + T_BH + (brow + np * 16) * 128
                            + (uint32_t)((((ks2 + bkseg) ^ r7b)) << 4);
                ldsm4(bh[np], bo);
                ldsm4(bl[np], bo + (T_BL - T_BH));
            }
#pragma unroll
            for (int mt = 0; mt < 4; mt++)
#pragma unroll
                for (int nt = 0; nt < 4; nt++) {
                    const int np = nt >> 1, hb = (nt & 1) * 2;
                    mma16816(acc[mt][nt], ah[mt],  bh[np][hb], bh[np][hb + 1]);
                    mma16816(acc[mt][nt], ah[mt],  bl[np][hb], bl[np][hb + 1]);
                    mma16816(acc[mt][nt], alr[mt], bh[np][hb], bh[np][hb + 1]);
                }
        }
        __syncthreads();
    }

    const int rr = lane >> 2, cc = (lane & 3) * 2;

    if constexpr (EPI == 1) {
#pragma unroll
        for (int mt = 0; mt < 4; mt++) {
            const long long m = m0 + wm + mt * 16 + rr;
#pragma unroll
            for (int nt = 0; nt < 4; nt++) {
                const int n = n0 + wn + nt * 8 + cc;
                float2 b2 = *(const float2*)(bias + n);
                float2 v0 = make_float2(acc[mt][nt][0] + b2.x, acc[mt][nt][1] + b2.y);
                float2 v1 = make_float2(acc[mt][nt][2] + b2.x, acc[mt][nt][3] + b2.y);
                *(float2*)(C + m * ldc + n)       = v0;
                *(float2*)(C + (m + 8) * ldc + n) = v1;
            }
        }
    } else if constexpr (EPI == 2) {
#pragma unroll
        for (int mt = 0; mt < 4; mt++) {
            const long long m = m0 + wm + mt * 16 + rr;
#pragma unroll
            for (int nt = 0; nt < 4; nt++) {
                const int n = n0 + wn + nt * 8 + cc;
                float* p0 = C + m * ldc + n;
                float* p1 = C + (m + 8) * ldc + n;
                atomicAdd(p0,     acc[mt][nt][0]);
                atomicAdd(p0 + 1, acc[mt][nt][1]);
                atomicAdd(p1,     acc[mt][nt][2]);
                atomicAdd(p1 + 1, acc[mt][nt][3]);
            }
        }
    } else {
        // ---- EPI == 3: fused softmax over m + norm + dual-layout bf16 split ----
        float* sf = (float*)smem;               // 128 x 133 fp32 tile
        // P0: stage accums (+score bias c) to SMEM
#pragma unroll
        for (int mt = 0; mt < 4; mt++) {
#pragma unroll
            for (int nt = 0; nt < 4; nt++) {
                int r = wm + mt * 16 + rr;
                int col = wn + nt * 8 + cc;
                float2 b2 = *(const float2*)(bias + n0 + col);
                sf[r * 133 + col]           = acc[mt][nt][0] + b2.x;
                sf[r * 133 + col + 1]       = acc[mt][nt][1] + b2.y;
                sf[(r + 8) * 133 + col]     = acc[mt][nt][2] + b2.x;
                sf[(r + 8) * 133 + col + 1] = acc[mt][nt][3] + b2.y;
            }
        }
        __syncthreads();
        // P1: row softmax (each thread owns one (row, head-half))
        {
            int row = tid & 127, hl = tid >> 7;
            size_t bn = (size_t)m0 + row;
            int headg = (n0 >> 6) + hl;
            float inv_t = 1.0f / g_T[bn * 16 + headg];
            float* rp = sf + row * 133 + hl * 64;
            float mx = -1e30f;
#pragma unroll 8
            for (int i = 0; i < 64; i++) mx = fmaxf(mx, rp[i]);
            float sum = 0.f;
#pragma unroll 8
            for (int i = 0; i < 64; i++) {
                float e = expf((rp[i] - mx) * inv_t);
                rp[i] = e; sum += e;
            }
            float inv = 1.0f / sum;
#pragma unroll 8
            for (int i = 0; i < 64; i++) rp[i] *= inv;
        }
        __syncthreads();
        const int bidx = m0 >> 13;
        // P2: per-hm norm partial (column sums) -> one atomic per hm
        {
            int col = tid & 127, half = tid >> 7;
            float s = 0.f;
#pragma unroll 8
            for (int i = 0; i < 64; i++) s += sf[(half * 64 + i) * 133 + col];
            float* snorm = sf + 128 * 133;
            snorm[half * 128 + col] = s;
            __syncthreads();
            if (tid < 128)
                atomicAdd(&g_norm[bidx * 1024 + n0 + tid], snorm[tid] + snorm[128 + tid]);
        }
        // P3: coalesced row-major Sh/Sl writes
#pragma unroll
        for (int i = 0; i < 32; i++) {
            int p = i * 256 + tid;
            int row = p >> 6, col = (p & 63) << 1;
            float w0 = sf[row * 133 + col], w1 = sf[row * 133 + col + 1];
            __nv_bfloat16 h0, l0, h1, l1;
            split2(w0, h0, l0); split2(w1, h1, l1);
            size_t o = ((size_t)m0 + row) * 1024 + n0 + col;
            *(__nv_bfloat162*)(g_Sh + o) = __nv_bfloat162(h0, h1);
            *(__nv_bfloat162*)(g_Sl + o) = __nv_bfloat162(l0, l1);
        }
        // P4: coalesced transposed Sth/Stl writes
        {
            int nb = m0 & 8191;
#pragma unroll
            for (int i = 0; i < 32; i++) {
                int p = i * 256 + tid;
                int hm = p >> 6, n2 = (p & 63) << 1;
                float w0 = sf[n2 * 133 + hm], w1 = sf[(n2 + 1) * 133 + hm];
                __nv_bfloat16 h0, l0, h1, l1;
                split2(w0, h0, l0); split2(w1, h1, l1);
                size_t o = ((size_t)bidx * 1024 + n0 + hm) * 8192 + nb + n2;
                *(__nv_bfloat162*)(g_Sth + o) = __nv_bfloat162(h0, h1);
                *(__nv_bfloat162*)(g_Stl + o) = __nv_bfloat162(l0, l1);
            }
        }
    }
}

// ============ aux kernels ============
__global__ void __launch_bounds__(256)
k_zero()
{
    size_t i = (size_t)blockIdx.x * 256 + threadIdx.x;   // 1M threads
    ((float4*)g_y)[i] = make_float4(0.f, 0.f, 0.f, 0.f);
    if (i < cB * cHM) g_norm[i] = 0.f;
}

__global__ void __launch_bounds__(256)
k_prep(const float* __restrict__ xq, const float* __restrict__ w_kv,
       const float* __restrict__ b_kv)
{
    int idx = blockIdx.x * 256 + threadIdx.x;
    int j = idx >> 10, hm = idx & 1023;
    int hbase = (hm >> 6) << 6;
    const float* xr = xq + (size_t)hm * 64;
    const float* wr = w_kv + (size_t)j * 2048 + hbase;
    float acc = 0.f;
#pragma unroll 8
    for (int d = 0; d < 64; d++) acc += xr[d] * wr[d];
    __nv_bfloat16 h, l; split2(acc, h, l);
    g_Ath[(size_t)hm * 1024 + j] = h;
    g_Atl[(size_t)hm * 1024 + j] = l;
    if (j == 0) {
        const float* br = b_kv + hbase;
        float cc = 0.f;
        for (int d = 0; d < 64; d++) cc += xr[d] * br[d];
        g_c[hm] = cc;
    }
}

__global__ void __launch_bounds__(256)
k_convx(const float* __restrict__ x)
{
    __shared__ __nv_bfloat16 sh[64][72];
    __shared__ __nv_bfloat16 sl[64][72];
    int jt = blockIdx.x, nt = blockIdx.y;
    int t = threadIdx.x;
    int r = t >> 2, c0 = (t & 3) * 16;
    size_t bn = (size_t)nt * 64 + r;
    const float* xr = x + bn * 1024 + jt * 64 + c0;
    __nv_bfloat16* dh = g_xh + bn * 1024 + jt * 64 + c0;
    __nv_bfloat16* dl = g_xl + bn * 1024 + jt * 64 + c0;
#pragma unroll
    for (int i = 0; i < 16; i += 2) {
        float2 v = *(const float2*)(xr + i);
        __nv_bfloat16 h0, l0, h1, l1;
        split2(v.x, h0, l0); split2(v.y, h1, l1);
        *(__nv_bfloat162*)(dh + i) = __nv_bfloat162(h0, h1);
        *(__nv_bfloat162*)(dl + i) = __nv_bfloat162(l0, l1);
        sh[r][c0 + i] = h0; sh[r][c0 + i + 1] = h1;
        sl[r][c0 + i] = l0; sl[r][c0 + i + 1] = l1;
    }
    __syncthreads();
    int b = (nt * 64) >> 13, nn0 = (nt * 64) & 8191;
    __nv_bfloat16* th = g_xth + ((size_t)(b * 1024 + jt * 64 + r)) * 8192 + nn0 + c0;
    __nv_bfloat16* tl = g_xtl + ((size_t)(b * 1024 + jt * 64 + r)) * 8192 + nn0 + c0;
#pragma unroll
    for (int i = 0; i < 16; i += 2) {
        *(__nv_bfloat162*)(th + i) = __nv_bfloat162(sh[c0 + i][r], sh[c0 + i + 1][r]);
        *(__nv_bfloat162*)(tl + i) = __nv_bfloat162(sl[c0 + i][r], sl[c0 + i + 1][r]);
    }
}

__global__ void __launch_bounds__(256)
k_temp(const float* __restrict__ x, const float* __restrict__ w_temp,
       const float* __restrict__ b_temp)
{
    int bn = blockIdx.x;
    __shared__ float xs[1024];
    __shared__ float part[256];
    int t = threadIdx.x;
    *(float4*)&xs[t * 4] = *(const float4*)(x + (size_t)bn * 1024 + t * 4);
    __syncthreads();
    int j0 = t >> 4, head = t & 15;
    float acc = 0.f;
#pragma unroll 8
    for (int i = 0; i < 64; i++) {
        int j = j0 + (i << 4);
        acc += xs[j] * w_temp[j * 16 + head];
    }
    part[t] = acc;
    __syncthreads();
    if (t < 16) {
        float s = 0.f;
#pragma unroll
        for (int g = 0; g < 16; g++) s += part[g * 16 + t];
        s += b_temp[t];
        float sp = fmaxf(s, 0.f) + log1pf(expf(-fabsf(s)));
        g_T[(size_t)bn * 16 + t] = 0.5f + sp;
    }
}

__global__ void __launch_bounds__(256)
k_st(const float* __restrict__ w_kv, const float* __restrict__ b_kv)
{
    int z = blockIdx.x;
    int b = z >> 4, h = z & 15;
    const float* Yb = g_y + ((size_t)b * 1024 + h * 64) * 1024;
    const float* Wv = w_kv + 1024 + h * 64;
    __shared__ float As[16][64];
    __shared__ float Bs[16][64];
    int t = threadIdx.x;
    int tyy = t >> 4, txx = t & 15;
    float acc[4][4] = {};
    for (int k0 = 0; k0 < 1024; k0 += 16) {
        {
            int m = t >> 2, k4 = (t & 3) << 2;
            float4 v = *(const float4*)(Yb + (size_t)m * 1024 + k0 + k4);
            As[k4 + 0][m] = v.x; As[k4 + 1][m] = v.y;
            As[k4 + 2][m] = v.z; As[k4 + 3][m] = v.w;
        }
        {
            int k = t >> 4, n4 = (t & 15) << 2;
            *(float4*)&Bs[k][n4] = *(const float4*)(Wv + (size_t)(k0 + k) * 2048 + n4);
        }
        __syncthreads();
#pragma unroll
        for (int kk = 0; kk < 16; kk++) {
            float4 a  = *(const float4*)&As[kk][tyy * 4];
            float4 bb = *(const float4*)&Bs[kk][txx * 4];
            float av[4] = {a.x, a.y, a.z, a.w};
            float bv[4] = {bb.x, bb.y, bb.z, bb.w};
#pragma unroll
            for (int i = 0; i < 4; i++)
#pragma unroll
                for (int jj = 0; jj < 4; jj++) acc[i][jj] += av[i] * bv[jj];
        }
        __syncthreads();
    }
#pragma unroll
    for (int i = 0; i < 4; i++) {
        int m = tyy * 4 + i;
        float nrm = g_norm[b * 1024 + h * 64 + m];
        float inv = 1.0f / (nrm + 1e-5f);
#pragma unroll
        for (int jj = 0; jj < 4; jj++) {
            int d = txx * 4 + jj;
            float bvv = b_kv[1024 + h * 64 + d];
            g_st[((size_t)z * 64 + m) * 64 + d] = (acc[i][jj] + nrm * bvv) * inv;
        }
    }
}

__global__ void __launch_bounds__(64)
k_qkv(const float* __restrict__ qkv_proj)
{
    int z = blockIdx.x;
    int h = (z >> 6) & 15;
    int d = threadIdx.x;
    __shared__ float st[64];
    __shared__ float ex[64];
    st[d] = g_st[(size_t)z * 64 + d];
    __syncthreads();
    const float* P = qkv_proj + (size_t)h * 64 * 192;
    float q = 0.f, k = 0.f, v = 0.f;
#pragma unroll 8
    for (int j = 0; j < 64; j++) {
        float s = st[j];
        const float* pr = P + j * 192;
        q += s * pr[d]; k += s * pr[64 + d]; v += s * pr[128 + d];
    }
    float dot = q * k * 0.125f;
    ex[d] = dot;
    __syncthreads();
    float mx = -1e30f;
    for (int j = 0; j < 64; j++) mx = fmaxf(mx, ex[j]);
    __syncthreads();
    float e = expf(dot - mx);
    ex[d] = e;
    __syncthreads();
    float sum = 0.f;
    for (int j = 0; j < 64; j++) sum += ex[j];
    g_ost[(size_t)z * 64 + d] = (e / sum) * v;
}

__global__ void __launch_bounds__(256)
k_zmat(const float* __restrict__ w_out)
{
    int z = blockIdx.y, jc = blockIdx.x;
    int b = z >> 4, h = z & 15;
    __shared__ float As[64][64];
    __shared__ float Bs[64][64];
    int t = threadIdx.x;
#pragma unroll
    for (int r = 0; r < 4; r++) {
        int lin = t + r * 256;
        int row = lin >> 4;
        int c4  = (lin & 15) << 2;
        float4 v = *(const float4*)(g_ost + ((size_t)z * 64 + row) * 64 + c4);
        As[c4 + 0][row] = v.x; As[c4 + 1][row] = v.y;
        As[c4 + 2][row] = v.z; As[c4 + 3][row] = v.w;
        *(float4*)&Bs[row][c4] =
            *(const float4*)(w_out + (size_t)(h * 64 + row) * 1024 + jc * 64 + c4);
    }
    __syncthreads();
    int tyy = t >> 4, txx = t & 15;
    float acc[4][4] = {};
#pragma unroll
    for (int kk = 0; kk < 64; kk++) {
        float4 a  = *(const float4*)&As[kk][tyy * 4];
        float4 bb = *(const float4*)&Bs[kk][txx * 4];
        float av[4] = {a.x, a.y, a.z, a.w};
        float bv[4] = {bb.x, bb.y, bb.z, bb.w};
#pragma unroll
        for (int i = 0; i < 4; i++)
#pragma unroll
            for (int jj = 0; jj < 4; jj++) acc[i][jj] += av[i] * bv[jj];
    }
#pragma unroll
    for (int i = 0; i < 4; i++) {
        int hm = h * 64 + tyy * 4 + i;
#pragma unroll
        for (int jj = 0; jj < 4; jj++) {
            int j = jc * 64 + txx * 4 + jj;
            __nv_bfloat16 hh, ll; split2(acc[i][jj], hh, ll);
            size_t o = ((size_t)b * 1024 + j) * 1024 + hm;
            g_Zth[o] = hh; g_Ztl[o] = ll;
        }
    }
}

// ---------------------------------------------------------------------------
extern "C" void kernel_launch(void* const* d_in, const int* in_sizes, int n_in,
                              void* d_out, int out_size)
{
    (void)in_sizes; (void)n_in; (void)out_size;
    const float* x      = (const float*)d_in[0];
    const float* w_kv   = (const float*)d_in[2];
    const float* b_kv   = (const float*)d_in[3];
    const float* w_temp = (const float*)d_in[4];
    const float* b_temp = (const float*)d_in[5];
    const float* xq     = (const float*)d_in[6];
    const float* qkv_p  = (const float*)d_in[7];
    const float* w_out  = (const float*)d_in[8];
    const float* b_out  = (const float*)d_in[9];
    float* out = (float*)d_out;

    float *pc, *py;
    __nv_bfloat16 *pxh, *pxl, *pxth, *pxtl, *pSh, *pSl, *pSth, *pStl, *pAth, *pAtl, *pZth, *pZtl;
    cudaGetSymbolAddress((void**)&pc,  g_c);
    cudaGetSymbolAddress((void**)&py,  g_y);
    cudaGetSymbolAddress((void**)&pxh, g_xh);   cudaGetSymbolAddress((void**)&pxl, g_xl);
    cudaGetSymbolAddress((void**)&pxth, g_xth); cudaGetSymbolAddress((void**)&pxtl, g_xtl);
    cudaGetSymbolAddress((void**)&pSh, g_Sh);   cudaGetSymbolAddress((void**)&pSl, g_Sl);
    cudaGetSymbolAddress((void**)&pSth, g_Sth); cudaGetSymbolAddress((void**)&pStl, g_Stl);
    cudaGetSymbolAddress((void**)&pAth, g_Ath); cudaGetSymbolAddress((void**)&pAtl, g_Atl);
    cudaGetSymbolAddress((void**)&pZth, g_Zth); cudaGetSymbolAddress((void**)&pZtl, g_Ztl);

    cudaFuncSetAttribute(mma_gemm<1>, cudaFuncAttributeMaxDynamicSharedMemorySize, GSMEM);
    cudaFuncSetAttribute(mma_gemm<2>, cudaFuncAttributeMaxDynamicSharedMemorySize, GSMEM);
    cudaFuncSetAttribute(mma_gemm<3>, cudaFuncAttributeMaxDynamicSharedMemorySize, GSMEM);

    k_zero<<<4096, 256>>>();
    k_prep<<<4096, 256>>>(xq, w_kv, b_kv);
    k_convx<<<dim3(16, 512), 256>>>(x);
    k_temp<<<cB * cN, 256>>>(x, w_temp, b_temp);
    // scores + fused softmax/norm/split:  S = x @ At^T + c  (M=32768,N=1024,K=1024)
    mma_gemm<3><<<dim3(8, 256, 1), 256, GSMEM>>>(
        pxh, pxl, pAth, pAtl, nullptr, pc, 1024, 1024, 1024, 0, 0, 0, 0, 0);
    // y[b] = S[b]^T @ x[b]  (M=1024,N=1024,K=8192), K-split x4 + atomic accumulate
    mma_gemm<2><<<dim3(8, 8, cB * 4), 256, GSMEM>>>(
        pSth, pStl, pxth, pxtl, py, nullptr, 2048, 8192, 8192, 1024,
        (long long)cHM * cN, (long long)cH * cN, (long long)cHM * cH, 2);
    k_st<<<cB * cNH, 256>>>(w_kv, b_kv);
    k_qkv<<<cB * cNH * 64, 64>>>(qkv_p);
    k_zmat<<<dim3(16, cB * cNH), 256>>>(w_out);
    // out[b] = S[b] @ Zt[b]^T + b_out  (M=8192,N=1024,K=1024)
    mma_gemm<1><<<dim3(8, 64, cB), 256, GSMEM>>>(
        pSh, pSl, pZth, pZtl, out, b_out, 1024, 1024, 1024, 1024,
        (long long)cN * cHM, (long long)cH * cHM, (long long)cN * cH, 0);
}